// round 1
// baseline (speedup 1.0000x reference)
#include <cuda_runtime.h>
#include <math.h>

#define B_   2
#define S_   2048
#define D_   768
#define H_   12
#define HD_  64
#define MTOT (B_*S_)   // 4096

// Scratch (allocation-free rule: __device__ globals)
__device__ float g_q[MTOT*D_];
__device__ float g_k[MTOT*D_];
__device__ float g_v[MTOT*D_];
__device__ float g_ctx[MTOT*D_];

// ---------------------------------------------------------------------------
// GEMM: C[M,768] = A[M,768] @ W[768,768] + bias   (M=4096)
// 64x64 block tile, BK=16, 256 threads, 4x4 micro-tile per thread.
// ---------------------------------------------------------------------------
__global__ __launch_bounds__(256) void gemm_bias_kernel(
    const float* __restrict__ A, const float* __restrict__ W,
    const float* __restrict__ bias, float* __restrict__ C)
{
    const int N = D_, K = D_;
    __shared__ float As[16][68];   // [k][m], padded (transposed A tile)
    __shared__ float Bs[16][68];   // [k][n], padded

    const int tid = threadIdx.x;
    const int m0 = blockIdx.x * 64;
    const int n0 = blockIdx.y * 64;

    const int tx4 = (tid & 15) * 4;   // n offset of micro-tile
    const int ty4 = (tid >> 4) * 4;   // m offset of micro-tile

    // loader indices
    const int alr = tid >> 2;          // 0..63 row of A tile
    const int alc = (tid & 3) * 4;     // 0..12 col (float4)
    const int blr = tid >> 4;          // 0..15 row of B tile
    const int blc = (tid & 15) * 4;    // 0..60 col (float4)

    float c[4][4];
#pragma unroll
    for (int i = 0; i < 4; i++)
#pragma unroll
        for (int j = 0; j < 4; j++) c[i][j] = 0.f;

    for (int k0 = 0; k0 < K; k0 += 16) {
        float4 av = *(const float4*)&A[(m0 + alr) * K + k0 + alc];
        As[alc + 0][alr] = av.x;
        As[alc + 1][alr] = av.y;
        As[alc + 2][alr] = av.z;
        As[alc + 3][alr] = av.w;
        *(float4*)&Bs[blr][blc] = *(const float4*)&W[(k0 + blr) * N + n0 + blc];
        __syncthreads();

#pragma unroll
        for (int kk = 0; kk < 16; kk++) {
            float4 a4 = *(const float4*)&As[kk][ty4];
            float4 b4 = *(const float4*)&Bs[kk][tx4];
            c[0][0] += a4.x * b4.x; c[0][1] += a4.x * b4.y; c[0][2] += a4.x * b4.z; c[0][3] += a4.x * b4.w;
            c[1][0] += a4.y * b4.x; c[1][1] += a4.y * b4.y; c[1][2] += a4.y * b4.z; c[1][3] += a4.y * b4.w;
            c[2][0] += a4.z * b4.x; c[2][1] += a4.z * b4.y; c[2][2] += a4.z * b4.z; c[2][3] += a4.z * b4.w;
            c[3][0] += a4.w * b4.x; c[3][1] += a4.w * b4.y; c[3][2] += a4.w * b4.z; c[3][3] += a4.w * b4.w;
        }
        __syncthreads();
    }

    float4 bv = *(const float4*)&bias[n0 + tx4];
#pragma unroll
    for (int i = 0; i < 4; i++) {
        float4 o;
        o.x = c[i][0] + bv.x;
        o.y = c[i][1] + bv.y;
        o.z = c[i][2] + bv.z;
        o.w = c[i][3] + bv.w;
        *(float4*)&C[(m0 + ty4 + i) * N + n0 + tx4] = o;
    }
}

// ---------------------------------------------------------------------------
// Flash attention: one block per (qtile, head, batch). 256 threads.
// 4 threads (a "quad") per query row; each thread owns 16 output dims.
// ---------------------------------------------------------------------------
#define KS_STRIDE 68   // 64 + 4 pad, float4-aligned; quad rows hit distinct banks
#define PS_STRIDE 65
#define ATTN_SMEM ((2 * 64 * KS_STRIDE + 64 * PS_STRIDE) * (int)sizeof(float))

__device__ __forceinline__ void fma4(float4& a, float p, float4 v) {
    a.x += p * v.x; a.y += p * v.y; a.z += p * v.z; a.w += p * v.w;
}
__device__ __forceinline__ void scl4(float4& a, float s) {
    a.x *= s; a.y *= s; a.z *= s; a.w *= s;
}

__global__ __launch_bounds__(256) void attn_kernel(
    const float* __restrict__ Q, const float* __restrict__ K,
    const float* __restrict__ V, float* __restrict__ O)
{
    extern __shared__ float smem[];
    float* Ks = smem;                     // 64 x KS_STRIDE
    float* Vs = smem + 64 * KS_STRIDE;    // 64 x KS_STRIDE
    float* Ps = smem + 2 * 64 * KS_STRIDE; // 64 x PS_STRIDE

    const int tid  = threadIdx.x;
    const int row  = tid >> 2;   // query row within tile, 0..63
    const int quad = tid & 3;    // 4 threads per row
    const int b = blockIdx.z, h = blockIdx.y, qt = blockIdx.x;
    const float scale = 0.125f;  // 1/sqrt(64)

    // q row in registers (64 floats)
    const float* qptr = Q + (size_t)(b * S_ + qt * 64 + row) * D_ + h * HD_;
    float4 q4[16];
#pragma unroll
    for (int i = 0; i < 16; i++) q4[i] = ((const float4*)qptr)[i];

    float4 acc[4];
#pragma unroll
    for (int i = 0; i < 4; i++) acc[i] = make_float4(0.f, 0.f, 0.f, 0.f);
    float mrow = -1e30f, lrow = 0.f;

    const int lr = row, lc = quad * 16;   // loader: each thread 16 floats of K and V

    for (int kt = 0; kt < S_ / 64; kt++) {
        const float* kp = K + (size_t)(b * S_ + kt * 64 + lr) * D_ + h * HD_ + lc;
        const float* vp = V + (size_t)(b * S_ + kt * 64 + lr) * D_ + h * HD_ + lc;
#pragma unroll
        for (int i = 0; i < 4; i++) {
            ((float4*)&Ks[lr * KS_STRIDE + lc])[i] = ((const float4*)kp)[i];
            ((float4*)&Vs[lr * KS_STRIDE + lc])[i] = ((const float4*)vp)[i];
        }
        __syncthreads();

        // scores for 16 keys (kk = 4*j + quad): conflict-free Ks reads
        float s[16];
#pragma unroll
        for (int j = 0; j < 16; j++) {
            const float4* kr = (const float4*)&Ks[(4 * j + quad) * KS_STRIDE];
            float d0 = 0.f, d1 = 0.f, d2 = 0.f, d3 = 0.f;
#pragma unroll
            for (int i = 0; i < 16; i++) {
                float4 kv = kr[i];
                d0 += q4[i].x * kv.x; d1 += q4[i].y * kv.y;
                d2 += q4[i].z * kv.z; d3 += q4[i].w * kv.w;
            }
            s[j] = ((d0 + d1) + (d2 + d3)) * scale;
        }

        // row max over 64 scores (16 local + quad shfl reduce)
        float mt = s[0];
#pragma unroll
        for (int j = 1; j < 16; j++) mt = fmaxf(mt, s[j]);
        mt = fmaxf(mt, __shfl_xor_sync(0xffffffffu, mt, 1));
        mt = fmaxf(mt, __shfl_xor_sync(0xffffffffu, mt, 2));

        float mnew = fmaxf(mrow, mt);
        float corr = __expf(mrow - mnew);

        float ps = 0.f;
#pragma unroll
        for (int j = 0; j < 16; j++) {
            float p = __expf(s[j] - mnew);
            ps += p;
            Ps[row * PS_STRIDE + 4 * j + quad] = p;
        }
        ps += __shfl_xor_sync(0xffffffffu, ps, 1);
        ps += __shfl_xor_sync(0xffffffffu, ps, 2);

        lrow = lrow * corr + ps;
        mrow = mnew;
#pragma unroll
        for (int i = 0; i < 4; i++) scl4(acc[i], corr);

        __syncthreads();   // Ps visible to whole quad's row readers

        // PV: each thread accumulates its 16 dims over all 64 keys
#pragma unroll 4
        for (int k = 0; k < 64; k++) {
            float p = Ps[row * PS_STRIDE + k];
            const float4* vr = (const float4*)&Vs[k * KS_STRIDE + quad * 16];
            fma4(acc[0], p, vr[0]);
            fma4(acc[1], p, vr[1]);
            fma4(acc[2], p, vr[2]);
            fma4(acc[3], p, vr[3]);
        }
        __syncthreads();   // done with Ks/Vs/Ps before next tile load
    }

    const float inv = 1.f / lrow;
    float* op = O + (size_t)(b * S_ + qt * 64 + row) * D_ + h * HD_ + quad * 16;
#pragma unroll
    for (int i = 0; i < 4; i++) {
        float4 o = acc[i];
        scl4(o, inv);
        ((float4*)op)[i] = o;
    }
}

// ---------------------------------------------------------------------------
extern "C" void kernel_launch(void* const* d_in, const int* in_sizes, int n_in,
                              void* d_out, int out_size)
{
    (void)in_sizes; (void)n_in; (void)out_size;
    const float* x  = (const float*)d_in[0];
    const float* Wq = (const float*)d_in[1];
    const float* bq = (const float*)d_in[2];
    const float* Wk = (const float*)d_in[3];
    const float* bk = (const float*)d_in[4];
    const float* Wv = (const float*)d_in[5];
    const float* bv = (const float*)d_in[6];
    const float* Wo = (const float*)d_in[7];
    const float* bo = (const float*)d_in[8];
    float* out = (float*)d_out;

    float *q, *k, *v, *ctx;
    cudaGetSymbolAddress((void**)&q,   g_q);
    cudaGetSymbolAddress((void**)&k,   g_k);
    cudaGetSymbolAddress((void**)&v,   g_v);
    cudaGetSymbolAddress((void**)&ctx, g_ctx);

    dim3 gemm_grid(MTOT / 64, D_ / 64);
    gemm_bias_kernel<<<gemm_grid, 256>>>(x, Wq, bq, q);
    gemm_bias_kernel<<<gemm_grid, 256>>>(x, Wk, bk, k);
    gemm_bias_kernel<<<gemm_grid, 256>>>(x, Wv, bv, v);

    cudaFuncSetAttribute(attn_kernel, cudaFuncAttributeMaxDynamicSharedMemorySize,
                         ATTN_SMEM);
    attn_kernel<<<dim3(S_ / 64, H_, B_), 256, ATTN_SMEM>>>(q, k, v, ctx);

    gemm_bias_kernel<<<gemm_grid, 256>>>(ctx, Wo, bo, out);
}

// round 2
// speedup vs baseline: 7.8313x; 7.8313x over previous
#include <cuda_runtime.h>
#include <cuda_fp16.h>

#define MTOT 4096
#define D_   768
#define H_   12
#define S_   2048

// ------------------------- scratch (__device__ globals) ---------------------
__device__ half g_xhi[MTOT * D_];
__device__ half g_xlo[MTOT * D_];
__device__ half g_wqkv_hi[3 * D_ * D_];   // [n=2304][k=768], B col-major (W^T)
__device__ half g_wqkv_lo[3 * D_ * D_];
__device__ half g_wo_hi[D_ * D_];
__device__ half g_wo_lo[D_ * D_];
__device__ half g_qkv[MTOT * 3 * D_];     // [token][2304]: q | k | v
__device__ half g_ctx_hi[MTOT * D_];
__device__ half g_ctx_lo[MTOT * D_];

// ------------------------- ptx helpers --------------------------------------
__device__ __forceinline__ void ldsm_x4(unsigned r[4], const void* p) {
    unsigned a = (unsigned)__cvta_generic_to_shared(p);
    asm volatile("ldmatrix.sync.aligned.m8n8.x4.shared.b16 {%0,%1,%2,%3}, [%4];\n"
                 : "=r"(r[0]), "=r"(r[1]), "=r"(r[2]), "=r"(r[3]) : "r"(a));
}
__device__ __forceinline__ void ldsm_x4_t(unsigned r[4], const void* p) {
    unsigned a = (unsigned)__cvta_generic_to_shared(p);
    asm volatile("ldmatrix.sync.aligned.m8n8.x4.trans.shared.b16 {%0,%1,%2,%3}, [%4];\n"
                 : "=r"(r[0]), "=r"(r[1]), "=r"(r[2]), "=r"(r[3]) : "r"(a));
}
__device__ __forceinline__ void mma16816(float c[4], const unsigned a[4], const unsigned b[2]) {
    asm volatile(
        "mma.sync.aligned.m16n8k16.row.col.f32.f16.f16.f32 "
        "{%0,%1,%2,%3}, {%4,%5,%6,%7}, {%8,%9}, {%0,%1,%2,%3};\n"
        : "+f"(c[0]), "+f"(c[1]), "+f"(c[2]), "+f"(c[3])
        : "r"(a[0]), "r"(a[1]), "r"(a[2]), "r"(a[3]), "r"(b[0]), "r"(b[1]));
}

// ------------------------- conversion kernels -------------------------------
__global__ void xsplit_kernel(const float* __restrict__ x,
                              half* __restrict__ hi, half* __restrict__ lo, int n) {
    int i = blockIdx.x * 256 + threadIdx.x;
    if (i < n) {
        float v = x[i];
        half h = __float2half_rn(v);
        hi[i] = h;
        lo[i] = __float2half_rn(v - __half2float(h));
    }
}

// W [k=768][n=768] fp32 row-major  ->  T [n][k] fp16 hi/lo (transposed split)
__global__ void wsplit_kernel(const float* __restrict__ W,
                              half* __restrict__ Thi, half* __restrict__ Tlo) {
    __shared__ float t[32][33];
    const int bx = blockIdx.x * 32;  // k
    const int by = blockIdx.y * 32;  // n
    const int x = threadIdx.x, y = threadIdx.y;
#pragma unroll
    for (int i = y; i < 32; i += 8)
        t[i][x] = W[(size_t)(bx + i) * D_ + by + x];
    __syncthreads();
#pragma unroll
    for (int i = y; i < 32; i += 8) {
        float v = t[x][i];                 // = W[bx+x][by+i]
        half hv = __float2half_rn(v);
        Thi[(size_t)(by + i) * D_ + bx + x] = hv;
        Tlo[(size_t)(by + i) * D_ + bx + x] = __float2half_rn(v - __half2float(hv));
    }
}

// ------------------------- split-fp16 GEMM ----------------------------------
// C[M=4096][N] = sum_seg A_seg[M][768] @ B_seg[N][768]^T + bias(col-segmented)
// Block tile 128x128, Kt=32, 8 warps, warp tile 64x32, double-buffered smem.
__global__ __launch_bounds__(256) void hgemm3(
    const half* __restrict__ A0c, const half* __restrict__ A1c, const half* __restrict__ A2c,
    const half* __restrict__ B0c, const half* __restrict__ B1c, const half* __restrict__ B2c,
    const float* __restrict__ bias0, const float* __restrict__ bias1,
    const float* __restrict__ bias2,
    void* __restrict__ Cout, int N, int outIsHalf)
{
    __shared__ half As[2][128][40];
    __shared__ half Bs[2][128][40];
    const int tid  = threadIdx.x;
    const int lane = tid & 31;
    const int w    = tid >> 5;
    const int wm   = (w >> 2) * 64;
    const int wn   = (w & 3) * 32;
    const int m0   = blockIdx.x * 128;
    const int n0   = blockIdx.y * 128;

    const half* Aseg[3] = {A0c, A1c, A2c};
    const half* Bseg[3] = {B0c, B1c, B2c};

    const int lr = tid >> 2;         // 0..63
    const int lk = (tid & 3) * 8;    // 0,8,16,24

    float c[4][4][4];
#pragma unroll
    for (int i = 0; i < 4; i++)
#pragma unroll
        for (int j = 0; j < 4; j++)
#pragma unroll
            for (int k = 0; k < 4; k++) c[i][j][k] = 0.f;

    // preload tile 0 (seg 0, k0 = 0)
    {
        const half* A = Aseg[0];
        const half* B = Bseg[0];
        *(float4*)&As[0][lr][lk]      = *(const float4*)&A[(size_t)(m0 + lr) * D_ + lk];
        *(float4*)&As[0][lr + 64][lk] = *(const float4*)&A[(size_t)(m0 + lr + 64) * D_ + lk];
        *(float4*)&Bs[0][lr][lk]      = *(const float4*)&B[(size_t)(n0 + lr) * D_ + lk];
        *(float4*)&Bs[0][lr + 64][lk] = *(const float4*)&B[(size_t)(n0 + lr + 64) * D_ + lk];
    }
    __syncthreads();

    const int NIT = 72;  // 3 segments x 24 k-tiles
    for (int it = 0; it < NIT; ++it) {
        const int cb = it & 1, nb = cb ^ 1;
        float4 a0v, a1v, b0v, b1v;
        const int itn = it + 1;
        if (itn < NIT) {
            const int segn = itn / 24;
            const int k0n  = (itn - segn * 24) * 32;
            const half* A = Aseg[segn];
            const half* B = Bseg[segn];
            a0v = *(const float4*)&A[(size_t)(m0 + lr) * D_ + k0n + lk];
            a1v = *(const float4*)&A[(size_t)(m0 + lr + 64) * D_ + k0n + lk];
            b0v = *(const float4*)&B[(size_t)(n0 + lr) * D_ + k0n + lk];
            b1v = *(const float4*)&B[(size_t)(n0 + lr + 64) * D_ + k0n + lk];
        }
#pragma unroll
        for (int kk = 0; kk < 2; ++kk) {
            unsigned a[4][4];
            unsigned b[4][2];
#pragma unroll
            for (int mf = 0; mf < 4; ++mf)
                ldsm_x4(a[mf], &As[cb][wm + mf * 16 + (lane & 15)][kk * 16 + (lane >> 4) * 8]);
#pragma unroll
            for (int bg = 0; bg < 2; ++bg) {
                unsigned r[4];
                ldsm_x4(r, &Bs[cb][wn + bg * 16 + ((lane & 7) | ((lane >> 4) << 3))]
                                   [kk * 16 + ((lane >> 3) & 1) * 8]);
                b[2 * bg][0] = r[0]; b[2 * bg][1] = r[1];
                b[2 * bg + 1][0] = r[2]; b[2 * bg + 1][1] = r[3];
            }
#pragma unroll
            for (int mf = 0; mf < 4; ++mf)
#pragma unroll
                for (int nf = 0; nf < 4; ++nf)
                    mma16816(c[mf][nf], a[mf], b[nf]);
        }
        if (itn < NIT) {
            *(float4*)&As[nb][lr][lk]      = a0v;
            *(float4*)&As[nb][lr + 64][lk] = a1v;
            *(float4*)&Bs[nb][lr][lk]      = b0v;
            *(float4*)&Bs[nb][lr + 64][lk] = b1v;
        }
        __syncthreads();
    }

    // epilogue: bias (column-segmented) + store
#pragma unroll
    for (int mf = 0; mf < 4; ++mf) {
#pragma unroll
        for (int nf = 0; nf < 4; ++nf) {
            const int row = m0 + wm + mf * 16 + (lane >> 2);
            const int col = n0 + wn + nf * 8 + 2 * (lane & 3);
            float bb0 = col < 768 ? bias0[col] : (col < 1536 ? bias1[col - 768] : bias2[col - 1536]);
            int c1i = col + 1;
            float bb1 = c1i < 768 ? bias0[c1i] : (c1i < 1536 ? bias1[c1i - 768] : bias2[c1i - 1536]);
            float v0 = c[mf][nf][0] + bb0, v1 = c[mf][nf][1] + bb1;
            float v2 = c[mf][nf][2] + bb0, v3 = c[mf][nf][3] + bb1;
            if (outIsHalf) {
                half* C = (half*)Cout;
                *(half2*)&C[(size_t)row * N + col]       = __floats2half2_rn(v0, v1);
                *(half2*)&C[(size_t)(row + 8) * N + col] = __floats2half2_rn(v2, v3);
            } else {
                float* C = (float*)Cout;
                *(float2*)&C[(size_t)row * N + col]       = make_float2(v0, v1);
                *(float2*)&C[(size_t)(row + 8) * N + col] = make_float2(v2, v3);
            }
        }
    }
}

// ------------------------- flash attention on HMMA --------------------------
// Block: 64 q-rows, 4 warps (warp = m16). K-tiles of 64 keys.
__global__ __launch_bounds__(128) void attn_mma(
    const half* __restrict__ qkv, half* __restrict__ ctxh, half* __restrict__ ctxl)
{
    __shared__ half Qs[64][72];
    __shared__ half Ks[64][72];
    __shared__ half Vs[64][72];
    const int tid  = threadIdx.x;
    const int lane = tid & 31;
    const int w    = tid >> 5;
    const int qt = blockIdx.x, h = blockIdx.y, b = blockIdx.z;
    const int tok0 = b * S_ + qt * 64;
    const int hoff = h * 64;
    const int lr = tid >> 1;            // 0..63
    const int lc = (tid & 1) * 32;      // half-row split

    // load Q tile (64x64 halves)
#pragma unroll
    for (int i = 0; i < 4; i++) {
        int kc = lc + i * 8;
        *(float4*)&Qs[lr][kc] = *(const float4*)&qkv[(size_t)(tok0 + lr) * 2304 + hoff + kc];
    }
    __syncthreads();
    unsigned qa[4][4];
#pragma unroll
    for (int kk = 0; kk < 4; kk++)
        ldsm_x4(qa[kk], &Qs[w * 16 + (lane & 15)][kk * 16 + (lane >> 4) * 8]);

    float acc[8][4];
#pragma unroll
    for (int i = 0; i < 8; i++)
#pragma unroll
        for (int j = 0; j < 4; j++) acc[i][j] = 0.f;
    float mlo = -1e30f, mhi = -1e30f, llo = 0.f, lhi = 0.f;

    for (int kt = 0; kt < S_ / 64; kt++) {
        __syncthreads();   // prior iter's ldsm done before overwrite
        const int kt0 = b * S_ + kt * 64;
#pragma unroll
        for (int i = 0; i < 4; i++) {
            int kc = lc + i * 8;
            *(float4*)&Ks[lr][kc] = *(const float4*)&qkv[(size_t)(kt0 + lr) * 2304 + 768 + hoff + kc];
            *(float4*)&Vs[lr][kc] = *(const float4*)&qkv[(size_t)(kt0 + lr) * 2304 + 1536 + hoff + kc];
        }
        __syncthreads();

        // S = Q @ K^T  (scores fp32)
        float sc[8][4];
#pragma unroll
        for (int i = 0; i < 8; i++)
#pragma unroll
            for (int j = 0; j < 4; j++) sc[i][j] = 0.f;
#pragma unroll
        for (int kk = 0; kk < 4; kk++) {
#pragma unroll
            for (int g = 0; g < 4; g++) {
                unsigned r[4];
                ldsm_x4(r, &Ks[g * 16 + ((lane & 7) | ((lane >> 4) << 3))]
                              [kk * 16 + ((lane >> 3) & 1) * 8]);
                unsigned b0[2] = {r[0], r[1]}, b1[2] = {r[2], r[3]};
                mma16816(sc[2 * g],     qa[kk], b0);
                mma16816(sc[2 * g + 1], qa[kk], b1);
            }
        }

        // online softmax (rows l>>2 and l>>2+8 per lane; quad = lanes l&3)
        float tlo = -1e30f, thi = -1e30f;
#pragma unroll
        for (int nf = 0; nf < 8; nf++) {
            tlo = fmaxf(tlo, fmaxf(sc[nf][0], sc[nf][1]));
            thi = fmaxf(thi, fmaxf(sc[nf][2], sc[nf][3]));
        }
        tlo *= 0.125f; thi *= 0.125f;
        tlo = fmaxf(tlo, __shfl_xor_sync(0xffffffffu, tlo, 1));
        tlo = fmaxf(tlo, __shfl_xor_sync(0xffffffffu, tlo, 2));
        thi = fmaxf(thi, __shfl_xor_sync(0xffffffffu, thi, 1));
        thi = fmaxf(thi, __shfl_xor_sync(0xffffffffu, thi, 2));
        float m2lo = fmaxf(mlo, tlo), m2hi = fmaxf(mhi, thi);
        float clo = __expf(mlo - m2lo), chi = __expf(mhi - m2hi);
        mlo = m2lo; mhi = m2hi;

        // P = exp(S*scale - m); pack C-frags directly into A-frags for PV
        unsigned pa[4][4];
        float slo = 0.f, shi = 0.f;
#pragma unroll
        for (int j = 0; j < 4; j++) {
#pragma unroll
            for (int t = 0; t < 2; t++) {
                const int nf = 2 * j + t;
                float p0 = __expf(sc[nf][0] * 0.125f - m2lo);
                float p1 = __expf(sc[nf][1] * 0.125f - m2lo);
                float p2 = __expf(sc[nf][2] * 0.125f - m2hi);
                float p3 = __expf(sc[nf][3] * 0.125f - m2hi);
                slo += p0 + p1; shi += p2 + p3;
                half2 hl = __floats2half2_rn(p0, p1);
                half2 hh = __floats2half2_rn(p2, p3);
                pa[j][2 * t]     = *reinterpret_cast<unsigned*>(&hl);
                pa[j][2 * t + 1] = *reinterpret_cast<unsigned*>(&hh);
            }
        }
        slo += __shfl_xor_sync(0xffffffffu, slo, 1);
        slo += __shfl_xor_sync(0xffffffffu, slo, 2);
        shi += __shfl_xor_sync(0xffffffffu, shi, 1);
        shi += __shfl_xor_sync(0xffffffffu, shi, 2);
        llo = llo * clo + slo;
        lhi = lhi * chi + shi;
#pragma unroll
        for (int nf = 0; nf < 8; nf++) {
            acc[nf][0] *= clo; acc[nf][1] *= clo;
            acc[nf][2] *= chi; acc[nf][3] *= chi;
        }

        // ctx += P @ V   (V via ldmatrix.trans)
#pragma unroll
        for (int j = 0; j < 4; j++) {
#pragma unroll
            for (int g = 0; g < 4; g++) {
                unsigned r[4];
                ldsm_x4_t(r, &Vs[j * 16 + (lane & 15)][g * 16 + (lane >> 4) * 8]);
                unsigned b0[2] = {r[0], r[1]}, b1[2] = {r[2], r[3]};
                mma16816(acc[2 * g],     pa[j], b0);
                mma16816(acc[2 * g + 1], pa[j], b1);
            }
        }
    }

    // epilogue: normalize, hi/lo split, store
    const float ilo = 1.f / llo, ihi = 1.f / lhi;
    const int row = tok0 + w * 16 + (lane >> 2);
#pragma unroll
    for (int nf = 0; nf < 8; nf++) {
        const int col = hoff + nf * 8 + 2 * (lane & 3);
        float o0 = acc[nf][0] * ilo, o1 = acc[nf][1] * ilo;
        float o2 = acc[nf][2] * ihi, o3 = acc[nf][3] * ihi;
        half h0 = __float2half_rn(o0), h1 = __float2half_rn(o1);
        half h2 = __float2half_rn(o2), h3 = __float2half_rn(o3);
        half e0 = __float2half_rn(o0 - __half2float(h0));
        half e1 = __float2half_rn(o1 - __half2float(h1));
        half e2 = __float2half_rn(o2 - __half2float(h2));
        half e3 = __float2half_rn(o3 - __half2float(h3));
        *(half2*)&ctxh[(size_t)row * D_ + col]       = __halves2half2(h0, h1);
        *(half2*)&ctxh[(size_t)(row + 8) * D_ + col] = __halves2half2(h2, h3);
        *(half2*)&ctxl[(size_t)row * D_ + col]       = __halves2half2(e0, e1);
        *(half2*)&ctxl[(size_t)(row + 8) * D_ + col] = __halves2half2(e2, e3);
    }
}

// ------------------------- launch -------------------------------------------
extern "C" void kernel_launch(void* const* d_in, const int* in_sizes, int n_in,
                              void* d_out, int out_size)
{
    (void)in_sizes; (void)n_in; (void)out_size;
    const float* x  = (const float*)d_in[0];
    const float* Wq = (const float*)d_in[1];
    const float* bq = (const float*)d_in[2];
    const float* Wk = (const float*)d_in[3];
    const float* bk = (const float*)d_in[4];
    const float* Wv = (const float*)d_in[5];
    const float* bv = (const float*)d_in[6];
    const float* Wo = (const float*)d_in[7];
    const float* bo = (const float*)d_in[8];
    float* out = (float*)d_out;

    half *xhi, *xlo, *wqh, *wql, *woh, *wol, *qkv, *cth, *ctl;
    cudaGetSymbolAddress((void**)&xhi, g_xhi);
    cudaGetSymbolAddress((void**)&xlo, g_xlo);
    cudaGetSymbolAddress((void**)&wqh, g_wqkv_hi);
    cudaGetSymbolAddress((void**)&wql, g_wqkv_lo);
    cudaGetSymbolAddress((void**)&woh, g_wo_hi);
    cudaGetSymbolAddress((void**)&wol, g_wo_lo);
    cudaGetSymbolAddress((void**)&qkv, g_qkv);
    cudaGetSymbolAddress((void**)&cth, g_ctx_hi);
    cudaGetSymbolAddress((void**)&ctl, g_ctx_lo);

    const int NX = MTOT * D_;
    xsplit_kernel<<<(NX + 255) / 256, 256>>>(x, xhi, xlo, NX);
    dim3 wgrid(24, 24), wblk(32, 8);
    wsplit_kernel<<<wgrid, wblk>>>(Wq, wqh,                 wql);
    wsplit_kernel<<<wgrid, wblk>>>(Wk, wqh + D_ * D_,       wql + D_ * D_);
    wsplit_kernel<<<wgrid, wblk>>>(Wv, wqh + 2 * D_ * D_,   wql + 2 * D_ * D_);
    wsplit_kernel<<<wgrid, wblk>>>(Wo, woh,                 wol);

    // QKV projection: [4096,2304] = split(x) @ split(Wqkv)
    hgemm3<<<dim3(32, 18), 256>>>(xhi, xlo, xhi,
                                  wqh, wqh, wql,
                                  bq, bk, bv,
                                  qkv, 2304, 1);

    attn_mma<<<dim3(S_ / 64, H_, 2), 128>>>(qkv, cth, ctl);

    // output projection (fp32 out)
    hgemm3<<<dim3(32, 6), 256>>>(cth, ctl, cth,
                                 woh, woh, wol,
                                 bo, bo, bo,
                                 out, 768, 0);
}

// round 4
// speedup vs baseline: 8.5095x; 1.0866x over previous
#include <cuda_runtime.h>
#include <cuda_fp16.h>
#include <cstdint>

#define MTOT 4096
#define D_   768
#define H_   12
#define S_   2048

// ------------------------- scratch (__device__ globals) ---------------------
__device__ half g_xhi[MTOT * D_];
__device__ half g_xlo[MTOT * D_];
__device__ half g_wqkv_hi[3 * D_ * D_];   // [n=2304][k=768]  (W^T, hi)
__device__ half g_wqkv_lo[3 * D_ * D_];
__device__ half g_wo_hi[D_ * D_];
__device__ half g_wo_lo[D_ * D_];
__device__ half g_qkv[MTOT * 3 * D_];     // [token][2304]: q | k | v
__device__ half g_ctx_hi[MTOT * D_];
__device__ half g_ctx_lo[MTOT * D_];

// ------------------------- ptx helpers --------------------------------------
__device__ __forceinline__ uint32_t smem_u32(const void* p) {
    return (uint32_t)__cvta_generic_to_shared(p);
}
__device__ __forceinline__ void ldsm_x4(unsigned r[4], const void* p) {
    unsigned a = smem_u32(p);
    asm volatile("ldmatrix.sync.aligned.m8n8.x4.shared.b16 {%0,%1,%2,%3}, [%4];\n"
                 : "=r"(r[0]), "=r"(r[1]), "=r"(r[2]), "=r"(r[3]) : "r"(a));
}
__device__ __forceinline__ void ldsm_x4_t(unsigned r[4], const void* p) {
    unsigned a = smem_u32(p);
    asm volatile("ldmatrix.sync.aligned.m8n8.x4.trans.shared.b16 {%0,%1,%2,%3}, [%4];\n"
                 : "=r"(r[0]), "=r"(r[1]), "=r"(r[2]), "=r"(r[3]) : "r"(a));
}
__device__ __forceinline__ void mma16816(float c[4], const unsigned a[4], const unsigned b[2]) {
    asm volatile(
        "mma.sync.aligned.m16n8k16.row.col.f32.f16.f16.f32 "
        "{%0,%1,%2,%3}, {%4,%5,%6,%7}, {%8,%9}, {%0,%1,%2,%3};\n"
        : "+f"(c[0]), "+f"(c[1]), "+f"(c[2]), "+f"(c[3])
        : "r"(a[0]), "r"(a[1]), "r"(a[2]), "r"(a[3]), "r"(b[0]), "r"(b[1]));
}

// ------------------------- conversion kernels -------------------------------
__global__ void xsplit_kernel(const float* __restrict__ x,
                              half* __restrict__ hi, half* __restrict__ lo, int n4) {
    int i = blockIdx.x * 256 + threadIdx.x;
    if (i < n4) {
        float4 v = ((const float4*)x)[i];
        half h0 = __float2half_rn(v.x), h1 = __float2half_rn(v.y);
        half h2 = __float2half_rn(v.z), h3 = __float2half_rn(v.w);
        ((half2*)hi)[2 * i]     = __halves2half2(h0, h1);
        ((half2*)hi)[2 * i + 1] = __halves2half2(h2, h3);
        ((half2*)lo)[2 * i] = __halves2half2(
            __float2half_rn(v.x - __half2float(h0)), __float2half_rn(v.y - __half2float(h1)));
        ((half2*)lo)[2 * i + 1] = __halves2half2(
            __float2half_rn(v.z - __half2float(h2)), __float2half_rn(v.w - __half2float(h3)));
    }
}

// W [k][n] fp32 -> T [n][k] fp16 hi/lo. 4 matrices in one launch (z index).
__global__ void wsplit4_kernel(const float* __restrict__ W0, const float* __restrict__ W1,
                               const float* __restrict__ W2, const float* __restrict__ W3,
                               half* __restrict__ qh, half* __restrict__ ql,
                               half* __restrict__ oh, half* __restrict__ ol) {
    __shared__ float t[32][33];
    const int z = blockIdx.z;
    const float* W = (z == 0) ? W0 : (z == 1) ? W1 : (z == 2) ? W2 : W3;
    half* Thi = (z < 3) ? qh + (size_t)z * D_ * D_ : oh;
    half* Tlo = (z < 3) ? ql + (size_t)z * D_ * D_ : ol;
    const int bx = blockIdx.x * 32;  // k
    const int by = blockIdx.y * 32;  // n
    const int x = threadIdx.x, y = threadIdx.y;
#pragma unroll
    for (int i = y; i < 32; i += 8)
        t[i][x] = W[(size_t)(bx + i) * D_ + by + x];
    __syncthreads();
#pragma unroll
    for (int i = y; i < 32; i += 8) {
        float v = t[x][i];
        half hv = __float2half_rn(v);
        Thi[(size_t)(by + i) * D_ + bx + x] = hv;
        Tlo[(size_t)(by + i) * D_ + bx + x] = __float2half_rn(v - __half2float(hv));
    }
}

// ------------------------- split-fp16 GEMM (HMMA) ----------------------------
// C[M=4096][N] = sum_seg A_seg[M][768] @ B_seg[N][768]^T + bias(col-segmented)
// Block tile 128x128, Kt=32, 8 warps, warp tile 64x32, double-buffered smem.
__global__ __launch_bounds__(256) void hgemm3(
    const half* __restrict__ A0c, const half* __restrict__ A1c, const half* __restrict__ A2c,
    const half* __restrict__ B0c, const half* __restrict__ B1c, const half* __restrict__ B2c,
    const float* __restrict__ bias0, const float* __restrict__ bias1,
    const float* __restrict__ bias2,
    void* __restrict__ Cout, int N, int outIsHalf)
{
    __shared__ half As[2][128][40];
    __shared__ half Bs[2][128][40];
    const int tid  = threadIdx.x;
    const int lane = tid & 31;
    const int w    = tid >> 5;
    const int wm   = (w >> 2) * 64;
    const int wn   = (w & 3) * 32;
    const int m0   = blockIdx.x * 128;
    const int n0   = blockIdx.y * 128;

    const half* Aseg[3] = {A0c, A1c, A2c};
    const half* Bseg[3] = {B0c, B1c, B2c};

    const int lr = tid >> 2;         // 0..63
    const int lk = (tid & 3) * 8;    // 0,8,16,24

    float c[4][4][4];
#pragma unroll
    for (int i = 0; i < 4; i++)
#pragma unroll
        for (int j = 0; j < 4; j++)
#pragma unroll
            for (int k = 0; k < 4; k++) c[i][j][k] = 0.f;

    {
        const half* A = Aseg[0];
        const half* B = Bseg[0];
        *(float4*)&As[0][lr][lk]      = *(const float4*)&A[(size_t)(m0 + lr) * D_ + lk];
        *(float4*)&As[0][lr + 64][lk] = *(const float4*)&A[(size_t)(m0 + lr + 64) * D_ + lk];
        *(float4*)&Bs[0][lr][lk]      = *(const float4*)&B[(size_t)(n0 + lr) * D_ + lk];
        *(float4*)&Bs[0][lr + 64][lk] = *(const float4*)&B[(size_t)(n0 + lr + 64) * D_ + lk];
    }
    __syncthreads();

    const int NIT = 72;  // 3 segments x 24 k-tiles
    for (int it = 0; it < NIT; ++it) {
        const int cb = it & 1, nb = cb ^ 1;
        float4 a0v, a1v, b0v, b1v;
        const int itn = it + 1;
        if (itn < NIT) {
            const int segn = itn / 24;
            const int k0n  = (itn - segn * 24) * 32;
            const half* A = Aseg[segn];
            const half* B = Bseg[segn];
            a0v = *(const float4*)&A[(size_t)(m0 + lr) * D_ + k0n + lk];
            a1v = *(const float4*)&A[(size_t)(m0 + lr + 64) * D_ + k0n + lk];
            b0v = *(const float4*)&B[(size_t)(n0 + lr) * D_ + k0n + lk];
            b1v = *(const float4*)&B[(size_t)(n0 + lr + 64) * D_ + k0n + lk];
        }
#pragma unroll
        for (int kk = 0; kk < 2; ++kk) {
            unsigned a[4][4];
            unsigned b[4][2];
#pragma unroll
            for (int mf = 0; mf < 4; ++mf)
                ldsm_x4(a[mf], &As[cb][wm + mf * 16 + (lane & 15)][kk * 16 + (lane >> 4) * 8]);
#pragma unroll
            for (int bg = 0; bg < 2; ++bg) {
                unsigned r[4];
                ldsm_x4(r, &Bs[cb][wn + bg * 16 + ((lane & 7) | ((lane >> 4) << 3))]
                                   [kk * 16 + ((lane >> 3) & 1) * 8]);
                b[2 * bg][0] = r[0]; b[2 * bg][1] = r[1];
                b[2 * bg + 1][0] = r[2]; b[2 * bg + 1][1] = r[3];
            }
#pragma unroll
            for (int mf = 0; mf < 4; ++mf)
#pragma unroll
                for (int nf = 0; nf < 4; ++nf)
                    mma16816(c[mf][nf], a[mf], b[nf]);
        }
        if (itn < NIT) {
            *(float4*)&As[nb][lr][lk]      = a0v;
            *(float4*)&As[nb][lr + 64][lk] = a1v;
            *(float4*)&Bs[nb][lr][lk]      = b0v;
            *(float4*)&Bs[nb][lr + 64][lk] = b1v;
        }
        __syncthreads();
    }

#pragma unroll
    for (int mf = 0; mf < 4; ++mf) {
#pragma unroll
        for (int nf = 0; nf < 4; ++nf) {
            const int row = m0 + wm + mf * 16 + (lane >> 2);
            const int col = n0 + wn + nf * 8 + 2 * (lane & 3);
            float bb0 = col < 768 ? bias0[col] : (col < 1536 ? bias1[col - 768] : bias2[col - 1536]);
            int c1i = col + 1;
            float bb1 = c1i < 768 ? bias0[c1i] : (c1i < 1536 ? bias1[c1i - 768] : bias2[c1i - 1536]);
            float v0 = c[mf][nf][0] + bb0, v1 = c[mf][nf][1] + bb1;
            float v2 = c[mf][nf][2] + bb0, v3 = c[mf][nf][3] + bb1;
            if (outIsHalf) {
                half* C = (half*)Cout;
                *(half2*)&C[(size_t)row * N + col]       = __floats2half2_rn(v0, v1);
                *(half2*)&C[(size_t)(row + 8) * N + col] = __floats2half2_rn(v2, v3);
            } else {
                float* C = (float*)Cout;
                *(float2*)&C[(size_t)row * N + col]       = make_float2(v0, v1);
                *(float2*)&C[(size_t)(row + 8) * N + col] = make_float2(v2, v3);
            }
        }
    }
}

// ------------------------- flash attention on HMMA --------------------------
// Block: 128 q-rows, 8 warps (warp = m16). K-tiles of 64 keys. 256 threads.
__global__ __launch_bounds__(256) void attn_mma(
    const half* __restrict__ qkv, half* __restrict__ ctxh, half* __restrict__ ctxl)
{
    __shared__ half Qs[128][72];
    __shared__ half Ks[64][72];
    __shared__ half Vs[64][72];
    const int tid  = threadIdx.x;
    const int lane = tid & 31;
    const int w    = tid >> 5;
    const int qt = blockIdx.x, h = blockIdx.y, b = blockIdx.z;
    const int tok0 = b * S_ + qt * 128;
    const int hoff = h * 64;

    // load Q tile (128x64 halves), folding in softmax scale 1/8 (exact in fp16)
    {
        const int lr = tid >> 1;           // 0..127
        const int lc = (tid & 1) * 32;
        const half2 s2 = __half2half2(__float2half(0.125f));
#pragma unroll
        for (int i = 0; i < 4; i++) {
            int kc = lc + i * 8;
            float4 v = *(const float4*)&qkv[(size_t)(tok0 + lr) * 2304 + hoff + kc];
            half2* hp = (half2*)&v;
#pragma unroll
            for (int q = 0; q < 4; q++) hp[q] = __hmul2(hp[q], s2);
            *(float4*)&Qs[lr][kc] = v;
        }
    }
    __syncthreads();
    unsigned qa[4][4];
#pragma unroll
    for (int kk = 0; kk < 4; kk++)
        ldsm_x4(qa[kk], &Qs[w * 16 + (lane & 15)][kk * 16 + (lane >> 4) * 8]);

    float acc[8][4];
#pragma unroll
    for (int i = 0; i < 8; i++)
#pragma unroll
        for (int j = 0; j < 4; j++) acc[i][j] = 0.f;
    float mlo = -1e30f, mhi = -1e30f, llo = 0.f, lhi = 0.f;

    const int lr2 = tid >> 2;           // 0..63
    const int lc2 = (tid & 3) * 16;

    for (int kt = 0; kt < S_ / 64; kt++) {
        __syncthreads();   // prior iter's ldsm done before overwrite
        const int kt0 = b * S_ + kt * 64;
        const half* kp = &qkv[(size_t)(kt0 + lr2) * 2304 + 768 + hoff + lc2];
        const half* vp = kp + 768;
#pragma unroll
        for (int i = 0; i < 2; i++) {
            *(float4*)&Ks[lr2][lc2 + i * 8] = *(const float4*)&kp[i * 8];
            *(float4*)&Vs[lr2][lc2 + i * 8] = *(const float4*)&vp[i * 8];
        }
        __syncthreads();

        // S = (Q*scale) @ K^T
        float sc[8][4];
#pragma unroll
        for (int i = 0; i < 8; i++)
#pragma unroll
            for (int j = 0; j < 4; j++) sc[i][j] = 0.f;
#pragma unroll
        for (int kk = 0; kk < 4; kk++) {
#pragma unroll
            for (int g = 0; g < 4; g++) {
                unsigned r[4];
                ldsm_x4(r, &Ks[g * 16 + ((lane & 7) | ((lane >> 4) << 3))]
                              [kk * 16 + ((lane >> 3) & 1) * 8]);
                unsigned b0[2] = {r[0], r[1]}, b1[2] = {r[2], r[3]};
                mma16816(sc[2 * g],     qa[kk], b0);
                mma16816(sc[2 * g + 1], qa[kk], b1);
            }
        }

        // online softmax
        float tlo = -1e30f, thi = -1e30f;
#pragma unroll
        for (int nf = 0; nf < 8; nf++) {
            tlo = fmaxf(tlo, fmaxf(sc[nf][0], sc[nf][1]));
            thi = fmaxf(thi, fmaxf(sc[nf][2], sc[nf][3]));
        }
        tlo = fmaxf(tlo, __shfl_xor_sync(0xffffffffu, tlo, 1));
        tlo = fmaxf(tlo, __shfl_xor_sync(0xffffffffu, tlo, 2));
        thi = fmaxf(thi, __shfl_xor_sync(0xffffffffu, thi, 1));
        thi = fmaxf(thi, __shfl_xor_sync(0xffffffffu, thi, 2));
        float m2lo = fmaxf(mlo, tlo), m2hi = fmaxf(mhi, thi);
        float clo = __expf(mlo - m2lo), chi = __expf(mhi - m2hi);
        mlo = m2lo; mhi = m2hi;

        unsigned pa[4][4];
        float slo = 0.f, shi = 0.f;
#pragma unroll
        for (int j = 0; j < 4; j++) {
#pragma unroll
            for (int t = 0; t < 2; t++) {
                const int nf = 2 * j + t;
                float p0 = __expf(sc[nf][0] - m2lo);
                float p1 = __expf(sc[nf][1] - m2lo);
                float p2 = __expf(sc[nf][2] - m2hi);
                float p3 = __expf(sc[nf][3] - m2hi);
                slo += p0 + p1; shi += p2 + p3;
                half2 hl = __floats2half2_rn(p0, p1);
                half2 hh = __floats2half2_rn(p2, p3);
                pa[j][2 * t]     = *reinterpret_cast<unsigned*>(&hl);
                pa[j][2 * t + 1] = *reinterpret_cast<unsigned*>(&hh);
            }
        }
        slo += __shfl_xor_sync(0xffffffffu, slo, 1);
        slo += __shfl_xor_sync(0xffffffffu, slo, 2);
        shi += __shfl_xor_sync(0xffffffffu, shi, 1);
        shi += __shfl_xor_sync(0xffffffffu, shi, 2);
        llo = llo * clo + slo;
        lhi = lhi * chi + shi;
#pragma unroll
        for (int nf = 0; nf < 8; nf++) {
            acc[nf][0] *= clo; acc[nf][1] *= clo;
            acc[nf][2] *= chi; acc[nf][3] *= chi;
        }

        // ctx += P @ V
#pragma unroll
        for (int j = 0; j < 4; j++) {
#pragma unroll
            for (int g = 0; g < 4; g++) {
                unsigned r[4];
                ldsm_x4_t(r, &Vs[j * 16 + (lane & 15)][g * 16 + (lane >> 4) * 8]);
                unsigned b0[2] = {r[0], r[1]}, b1[2] = {r[2], r[3]};
                mma16816(acc[2 * g],     pa[j], b0);
                mma16816(acc[2 * g + 1], pa[j], b1);
            }
        }
    }

    // epilogue: normalize, hi/lo split, store
    const float ilo = 1.f / llo, ihi = 1.f / lhi;
    const int row = tok0 + w * 16 + (lane >> 2);
#pragma unroll
    for (int nf = 0; nf < 8; nf++) {
        const int col = hoff + nf * 8 + 2 * (lane & 3);
        float o0 = acc[nf][0] * ilo, o1 = acc[nf][1] * ilo;
        float o2 = acc[nf][2] * ihi, o3 = acc[nf][3] * ihi;
        half h0 = __float2half_rn(o0), h1 = __float2half_rn(o1);
        half h2 = __float2half_rn(o2), h3 = __float2half_rn(o3);
        half e0 = __float2half_rn(o0 - __half2float(h0));
        half e1 = __float2half_rn(o1 - __half2float(h1));
        half e2 = __float2half_rn(o2 - __half2float(h2));
        half e3 = __float2half_rn(o3 - __half2float(h3));
        *(half2*)&ctxh[(size_t)row * D_ + col]       = __halves2half2(h0, h1);
        *(half2*)&ctxh[(size_t)(row + 8) * D_ + col] = __halves2half2(h2, h3);
        *(half2*)&ctxl[(size_t)row * D_ + col]       = __halves2half2(e0, e1);
        *(half2*)&ctxl[(size_t)(row + 8) * D_ + col] = __halves2half2(e2, e3);
    }
}

// ------------------------- launch -------------------------------------------
extern "C" void kernel_launch(void* const* d_in, const int* in_sizes, int n_in,
                              void* d_out, int out_size)
{
    (void)in_sizes; (void)n_in; (void)out_size;
    const float* x  = (const float*)d_in[0];
    const float* Wq = (const float*)d_in[1];
    const float* bq = (const float*)d_in[2];
    const float* Wk = (const float*)d_in[3];
    const float* bk = (const float*)d_in[4];
    const float* Wv = (const float*)d_in[5];
    const float* bv = (const float*)d_in[6];
    const float* Wo = (const float*)d_in[7];
    const float* bo = (const float*)d_in[8];
    float* out = (float*)d_out;

    half *xhi, *xlo, *wqh, *wql, *woh, *wol, *qkv, *cth, *ctl;
    cudaGetSymbolAddress((void**)&xhi, g_xhi);
    cudaGetSymbolAddress((void**)&xlo, g_xlo);
    cudaGetSymbolAddress((void**)&wqh, g_wqkv_hi);
    cudaGetSymbolAddress((void**)&wql, g_wqkv_lo);
    cudaGetSymbolAddress((void**)&woh, g_wo_hi);
    cudaGetSymbolAddress((void**)&wol, g_wo_lo);
    cudaGetSymbolAddress((void**)&qkv, g_qkv);
    cudaGetSymbolAddress((void**)&cth, g_ctx_hi);
    cudaGetSymbolAddress((void**)&ctl, g_ctx_lo);

    const int N4 = MTOT * D_ / 4;
    xsplit_kernel<<<(N4 + 255) / 256, 256>>>(x, xhi, xlo, N4);
    wsplit4_kernel<<<dim3(24, 24, 4), dim3(32, 8)>>>(Wq, Wk, Wv, Wo, wqh, wql, woh, wol);

    // QKV projection: [4096,2304] = xhi@Whi^T + xlo@Whi^T + xhi@Wlo^T
    hgemm3<<<dim3(32, 18), 256>>>(xhi, xlo, xhi,
                                  wqh, wqh, wql,
                                  bq, bk, bv,
                                  qkv, 2304, 1);

    attn_mma<<<dim3(S_ / 128, H_, 2), 256>>>(qkv, cth, ctl);

    // output projection (fp32 out)
    hgemm3<<<dim3(32, 6), 256>>>(cth, ctl, cth,
                                 woh, woh, wol,
                                 bo, bo, bo,
                                 out, 768, 0);
}

// round 5
// speedup vs baseline: 8.7509x; 1.0284x over previous
#include <cuda_runtime.h>
#include <cuda_fp16.h>
#include <cstdint>

#define MTOT 4096
#define D_   768
#define H_   12
#define S_   2048

// ------------------------- scratch (__device__ globals) ---------------------
__device__ half g_xhi[MTOT * D_];
__device__ half g_xlo[MTOT * D_];
__device__ half g_wqkv_hi[3 * D_ * D_];   // [n=2304][k=768]  (W^T, hi)
__device__ half g_wqkv_lo[3 * D_ * D_];
__device__ half g_wo_hi[D_ * D_];
__device__ half g_wo_lo[D_ * D_];
__device__ half g_qkv[MTOT * 3 * D_];     // [token][2304]: q | k | v
__device__ half g_ctx[MTOT * D_];

// ------------------------- ptx helpers --------------------------------------
__device__ __forceinline__ uint32_t smem_u32(const void* p) {
    return (uint32_t)__cvta_generic_to_shared(p);
}
__device__ __forceinline__ void ldsm_x4(unsigned r[4], const void* p) {
    unsigned a = smem_u32(p);
    asm volatile("ldmatrix.sync.aligned.m8n8.x4.shared.b16 {%0,%1,%2,%3}, [%4];\n"
                 : "=r"(r[0]), "=r"(r[1]), "=r"(r[2]), "=r"(r[3]) : "r"(a));
}
__device__ __forceinline__ void ldsm_x4_t(unsigned r[4], const void* p) {
    unsigned a = smem_u32(p);
    asm volatile("ldmatrix.sync.aligned.m8n8.x4.trans.shared.b16 {%0,%1,%2,%3}, [%4];\n"
                 : "=r"(r[0]), "=r"(r[1]), "=r"(r[2]), "=r"(r[3]) : "r"(a));
}
__device__ __forceinline__ void mma16816(float c[4], const unsigned a[4], const unsigned b[2]) {
    asm volatile(
        "mma.sync.aligned.m16n8k16.row.col.f32.f16.f16.f32 "
        "{%0,%1,%2,%3}, {%4,%5,%6,%7}, {%8,%9}, {%0,%1,%2,%3};\n"
        : "+f"(c[0]), "+f"(c[1]), "+f"(c[2]), "+f"(c[3])
        : "r"(a[0]), "r"(a[1]), "r"(a[2]), "r"(a[3]), "r"(b[0]), "r"(b[1]));
}
__device__ __forceinline__ void cp_async16(uint32_t dst, const void* src) {
    asm volatile("cp.async.cg.shared.global [%0], [%1], 16;\n" :: "r"(dst), "l"(src));
}
__device__ __forceinline__ void cp_commit() {
    asm volatile("cp.async.commit_group;\n");
}
template<int N> __device__ __forceinline__ void cp_wait() {
    asm volatile("cp.async.wait_group %0;\n" :: "n"(N) : "memory");
}
__device__ __forceinline__ float ex2(float x) {
    float y;
    asm("ex2.approx.ftz.f32 %0, %1;" : "=f"(y) : "f"(x));
    return y;
}

// ------------------------- conversion kernels -------------------------------
__global__ void xsplit_kernel(const float* __restrict__ x,
                              half* __restrict__ hi, half* __restrict__ lo, int n4) {
    int i = blockIdx.x * 256 + threadIdx.x;
    if (i < n4) {
        float4 v = ((const float4*)x)[i];
        half h0 = __float2half_rn(v.x), h1 = __float2half_rn(v.y);
        half h2 = __float2half_rn(v.z), h3 = __float2half_rn(v.w);
        ((half2*)hi)[2 * i]     = __halves2half2(h0, h1);
        ((half2*)hi)[2 * i + 1] = __halves2half2(h2, h3);
        ((half2*)lo)[2 * i] = __halves2half2(
            __float2half_rn(v.x - __half2float(h0)), __float2half_rn(v.y - __half2float(h1)));
        ((half2*)lo)[2 * i + 1] = __halves2half2(
            __float2half_rn(v.z - __half2float(h2)), __float2half_rn(v.w - __half2float(h3)));
    }
}

// W [k][n] fp32 -> T [n][k] fp16 hi/lo. 4 matrices in one launch (z index).
__global__ void wsplit4_kernel(const float* __restrict__ W0, const float* __restrict__ W1,
                               const float* __restrict__ W2, const float* __restrict__ W3,
                               half* __restrict__ qh, half* __restrict__ ql,
                               half* __restrict__ oh, half* __restrict__ ol) {
    __shared__ float t[32][33];
    const int z = blockIdx.z;
    const float* W = (z == 0) ? W0 : (z == 1) ? W1 : (z == 2) ? W2 : W3;
    half* Thi = (z < 3) ? qh + (size_t)z * D_ * D_ : oh;
    half* Tlo = (z < 3) ? ql + (size_t)z * D_ * D_ : ol;
    const int bx = blockIdx.x * 32;  // k
    const int by = blockIdx.y * 32;  // n
    const int x = threadIdx.x, y = threadIdx.y;
#pragma unroll
    for (int i = y; i < 32; i += 8)
        t[i][x] = W[(size_t)(bx + i) * D_ + by + x];
    __syncthreads();
#pragma unroll
    for (int i = y; i < 32; i += 8) {
        float v = t[x][i];
        half hv = __float2half_rn(v);
        Thi[(size_t)(by + i) * D_ + bx + x] = hv;
        Tlo[(size_t)(by + i) * D_ + bx + x] = __float2half_rn(v - __half2float(hv));
    }
}

// ------------------------- split-fp16 GEMM (HMMA, cp.async) ------------------
// C[M=4096][N] = sum_{seg<nseg} A_seg[M][768] @ B_seg[N][768]^T + bias
// Block tile 128x128, Kt=32, 8 warps, warp tile 64x32, cp.async double buffer.
__global__ __launch_bounds__(256) void hgemm3(
    const half* __restrict__ A0c, const half* __restrict__ A1c, const half* __restrict__ A2c,
    const half* __restrict__ B0c, const half* __restrict__ B1c, const half* __restrict__ B2c,
    const float* __restrict__ bias0, const float* __restrict__ bias1,
    const float* __restrict__ bias2,
    void* __restrict__ Cout, int N, int outIsHalf, int nseg)
{
    __shared__ __align__(16) half As[2][128][40];
    __shared__ __align__(16) half Bs[2][128][40];
    const int tid  = threadIdx.x;
    const int lane = tid & 31;
    const int w    = tid >> 5;
    const int wm   = (w >> 2) * 64;
    const int wn   = (w & 3) * 32;
    const int m0   = blockIdx.x * 128;
    const int n0   = blockIdx.y * 128;

    const half* Aseg[3] = {A0c, A1c, A2c};
    const half* Bseg[3] = {B0c, B1c, B2c};
    const int NIT = nseg * 24;

    // loader: row = tid>>1 (0..127), halves offset (tid&1)*16 + 8i
    const int plr = tid >> 1;
    const int plc = (tid & 1) * 16;

    auto prefetch = [&](int it, int buf) {
        const int seg = it / 24;
        const int k0  = (it - seg * 24) * 32;
        const half* Ag = Aseg[seg] + (size_t)(m0 + plr) * D_ + k0 + plc;
        const half* Bg = Bseg[seg] + (size_t)(n0 + plr) * D_ + k0 + plc;
        uint32_t ad = smem_u32(&As[buf][plr][plc]);
        uint32_t bd = smem_u32(&Bs[buf][plr][plc]);
        cp_async16(ad, Ag);      cp_async16(ad + 16, Ag + 8);
        cp_async16(bd, Bg);      cp_async16(bd + 16, Bg + 8);
        cp_commit();
    };

    float c[4][4][4];
#pragma unroll
    for (int i = 0; i < 4; i++)
#pragma unroll
        for (int j = 0; j < 4; j++)
#pragma unroll
            for (int k = 0; k < 4; k++) c[i][j][k] = 0.f;

    prefetch(0, 0);
    prefetch(1, 1);

    for (int it = 0; it < NIT; ++it) {
        const int cb = it & 1;
        if (it < NIT - 1) cp_wait<1>(); else cp_wait<0>();
        __syncthreads();

#pragma unroll
        for (int kk = 0; kk < 2; ++kk) {
            unsigned a[4][4];
            unsigned b[4][2];
#pragma unroll
            for (int mf = 0; mf < 4; ++mf)
                ldsm_x4(a[mf], &As[cb][wm + mf * 16 + (lane & 15)][kk * 16 + (lane >> 4) * 8]);
#pragma unroll
            for (int bg = 0; bg < 2; ++bg) {
                unsigned r[4];
                ldsm_x4(r, &Bs[cb][wn + bg * 16 + ((lane & 7) | ((lane >> 4) << 3))]
                                   [kk * 16 + ((lane >> 3) & 1) * 8]);
                b[2 * bg][0] = r[0]; b[2 * bg][1] = r[1];
                b[2 * bg + 1][0] = r[2]; b[2 * bg + 1][1] = r[3];
            }
#pragma unroll
            for (int mf = 0; mf < 4; ++mf)
#pragma unroll
                for (int nf = 0; nf < 4; ++nf)
                    mma16816(c[mf][nf], a[mf], b[nf]);
        }
        __syncthreads();
        if (it + 2 < NIT) prefetch(it + 2, cb);
    }

    // epilogue: bias (column-segmented) + store
#pragma unroll
    for (int mf = 0; mf < 4; ++mf) {
#pragma unroll
        for (int nf = 0; nf < 4; ++nf) {
            const int row = m0 + wm + mf * 16 + (lane >> 2);
            const int col = n0 + wn + nf * 8 + 2 * (lane & 3);
            float bb0 = col < 768 ? bias0[col] : (col < 1536 ? bias1[col - 768] : bias2[col - 1536]);
            int c1i = col + 1;
            float bb1 = c1i < 768 ? bias0[c1i] : (c1i < 1536 ? bias1[c1i - 768] : bias2[c1i - 1536]);
            float v0 = c[mf][nf][0] + bb0, v1 = c[mf][nf][1] + bb1;
            float v2 = c[mf][nf][2] + bb0, v3 = c[mf][nf][3] + bb1;
            if (outIsHalf) {
                half* C = (half*)Cout;
                *(half2*)&C[(size_t)row * N + col]       = __floats2half2_rn(v0, v1);
                *(half2*)&C[(size_t)(row + 8) * N + col] = __floats2half2_rn(v2, v3);
            } else {
                float* C = (float*)Cout;
                *(float2*)&C[(size_t)row * N + col]       = make_float2(v0, v1);
                *(float2*)&C[(size_t)(row + 8) * N + col] = make_float2(v2, v3);
            }
        }
    }
}

// ------------------------- flash attention on HMMA (cp.async) ---------------
// Block: 128 q-rows, 8 warps. K-tiles of 64 keys, double-buffered via cp.async.
// Softmax in log2 domain (scale*log2e folded into Q).
__global__ __launch_bounds__(256) void attn_mma(
    const half* __restrict__ qkv, half* __restrict__ ctx)
{
    // KV[buf][0]=K tile, KV[buf][1]=V tile (64x72 each). Q staging aliases KV.
    __shared__ __align__(16) half KV[2][2][64][72];
    half (*Qs)[72] = reinterpret_cast<half(*)[72]>(&KV[0][0][0][0]);  // 128x72

    const int tid  = threadIdx.x;
    const int lane = tid & 31;
    const int w    = tid >> 5;
    const int qt = blockIdx.x, h = blockIdx.y, b = blockIdx.z;
    const int tok0 = b * S_ + qt * 128;
    const int hoff = h * 64;

    // load Q tile (128x64), folding softmax scale * log2(e) into Q
    {
        const int lr = tid >> 1;
        const int lc = (tid & 1) * 32;
        const half2 s2 = __half2half2(__float2half(0.125f * 1.4426950408889634f));
#pragma unroll
        for (int i = 0; i < 4; i++) {
            int kc = lc + i * 8;
            float4 v = *(const float4*)&qkv[(size_t)(tok0 + lr) * 2304 + hoff + kc];
            half2* hp = (half2*)&v;
#pragma unroll
            for (int q = 0; q < 4; q++) hp[q] = __hmul2(hp[q], s2);
            *(float4*)&Qs[lr][kc] = v;
        }
    }
    __syncthreads();
    unsigned qa[4][4];
#pragma unroll
    for (int kk = 0; kk < 4; kk++)
        ldsm_x4(qa[kk], &Qs[w * 16 + (lane & 15)][kk * 16 + (lane >> 4) * 8]);
    __syncthreads();   // all warps done reading Q before cp.async overwrites

    // K/V prefetch: thread loads K row r halves [cq*16, cq*16+16) and same for V
    const int pr = tid >> 2;
    const int pc = (tid & 3) * 16;
    auto prefetch = [&](int kt, int buf) {
        const int kt0 = b * S_ + kt * 64;
        const half* kp = &qkv[(size_t)(kt0 + pr) * 2304 + 768 + hoff + pc];
        uint32_t kd = smem_u32(&KV[buf][0][pr][pc]);
        uint32_t vd = smem_u32(&KV[buf][1][pr][pc]);
        cp_async16(kd, kp);      cp_async16(kd + 16, kp + 8);
        cp_async16(vd, kp + 768); cp_async16(vd + 16, kp + 776);
        cp_commit();
    };

    float acc[8][4];
#pragma unroll
    for (int i = 0; i < 8; i++)
#pragma unroll
        for (int j = 0; j < 4; j++) acc[i][j] = 0.f;
    float mlo = -1e30f, mhi = -1e30f, llo = 0.f, lhi = 0.f;

    prefetch(0, 0);
    prefetch(1, 1);

    const int NT = S_ / 64;
    for (int kt = 0; kt < NT; kt++) {
        const int cb = kt & 1;
        if (kt < NT - 1) cp_wait<1>(); else cp_wait<0>();
        __syncthreads();
        half (*Ks)[72] = KV[cb][0];
        half (*Vs)[72] = KV[cb][1];

        // S_log2 = (Q*scale*log2e) @ K^T
        float sc[8][4];
#pragma unroll
        for (int i = 0; i < 8; i++)
#pragma unroll
            for (int j = 0; j < 4; j++) sc[i][j] = 0.f;
#pragma unroll
        for (int kk = 0; kk < 4; kk++) {
#pragma unroll
            for (int g = 0; g < 4; g++) {
                unsigned r[4];
                ldsm_x4(r, &Ks[g * 16 + ((lane & 7) | ((lane >> 4) << 3))]
                              [kk * 16 + ((lane >> 3) & 1) * 8]);
                unsigned b0[2] = {r[0], r[1]}, b1[2] = {r[2], r[3]};
                mma16816(sc[2 * g],     qa[kk], b0);
                mma16816(sc[2 * g + 1], qa[kk], b1);
            }
        }

        // online softmax in log2 domain
        float tlo = -1e30f, thi = -1e30f;
#pragma unroll
        for (int nf = 0; nf < 8; nf++) {
            tlo = fmaxf(tlo, fmaxf(sc[nf][0], sc[nf][1]));
            thi = fmaxf(thi, fmaxf(sc[nf][2], sc[nf][3]));
        }
        tlo = fmaxf(tlo, __shfl_xor_sync(0xffffffffu, tlo, 1));
        tlo = fmaxf(tlo, __shfl_xor_sync(0xffffffffu, tlo, 2));
        thi = fmaxf(thi, __shfl_xor_sync(0xffffffffu, thi, 1));
        thi = fmaxf(thi, __shfl_xor_sync(0xffffffffu, thi, 2));
        float m2lo = fmaxf(mlo, tlo), m2hi = fmaxf(mhi, thi);
        float clo = ex2(mlo - m2lo), chi = ex2(mhi - m2hi);
        mlo = m2lo; mhi = m2hi;

        unsigned pa[4][4];
        float slo = 0.f, shi = 0.f;
#pragma unroll
        for (int j = 0; j < 4; j++) {
#pragma unroll
            for (int t = 0; t < 2; t++) {
                const int nf = 2 * j + t;
                float p0 = ex2(sc[nf][0] - m2lo);
                float p1 = ex2(sc[nf][1] - m2lo);
                float p2 = ex2(sc[nf][2] - m2hi);
                float p3 = ex2(sc[nf][3] - m2hi);
                slo += p0 + p1; shi += p2 + p3;
                half2 hl = __floats2half2_rn(p0, p1);
                half2 hh = __floats2half2_rn(p2, p3);
                pa[j][2 * t]     = *reinterpret_cast<unsigned*>(&hl);
                pa[j][2 * t + 1] = *reinterpret_cast<unsigned*>(&hh);
            }
        }
        slo += __shfl_xor_sync(0xffffffffu, slo, 1);
        slo += __shfl_xor_sync(0xffffffffu, slo, 2);
        shi += __shfl_xor_sync(0xffffffffu, shi, 1);
        shi += __shfl_xor_sync(0xffffffffu, shi, 2);
        llo = llo * clo + slo;
        lhi = lhi * chi + shi;
#pragma unroll
        for (int nf = 0; nf < 8; nf++) {
            acc[nf][0] *= clo; acc[nf][1] *= clo;
            acc[nf][2] *= chi; acc[nf][3] *= chi;
        }

        // ctx += P @ V
#pragma unroll
        for (int j = 0; j < 4; j++) {
#pragma unroll
            for (int g = 0; g < 4; g++) {
                unsigned r[4];
                ldsm_x4_t(r, &Vs[j * 16 + (lane & 15)][g * 16 + (lane >> 4) * 8]);
                unsigned b0[2] = {r[0], r[1]}, b1[2] = {r[2], r[3]};
                mma16816(acc[2 * g],     pa[j], b0);
                mma16816(acc[2 * g + 1], pa[j], b1);
            }
        }
        __syncthreads();
        if (kt + 2 < NT) prefetch(kt + 2, cb);
    }

    // epilogue: normalize, store fp16 ctx
    const float ilo = 1.f / llo, ihi = 1.f / lhi;
    const int row = tok0 + w * 16 + (lane >> 2);
#pragma unroll
    for (int nf = 0; nf < 8; nf++) {
        const int col = hoff + nf * 8 + 2 * (lane & 3);
        *(half2*)&ctx[(size_t)row * D_ + col] =
            __floats2half2_rn(acc[nf][0] * ilo, acc[nf][1] * ilo);
        *(half2*)&ctx[(size_t)(row + 8) * D_ + col] =
            __floats2half2_rn(acc[nf][2] * ihi, acc[nf][3] * ihi);
    }
}

// ------------------------- launch -------------------------------------------
extern "C" void kernel_launch(void* const* d_in, const int* in_sizes, int n_in,
                              void* d_out, int out_size)
{
    (void)in_sizes; (void)n_in; (void)out_size;
    const float* x  = (const float*)d_in[0];
    const float* Wq = (const float*)d_in[1];
    const float* bq = (const float*)d_in[2];
    const float* Wk = (const float*)d_in[3];
    const float* bk = (const float*)d_in[4];
    const float* Wv = (const float*)d_in[5];
    const float* bv = (const float*)d_in[6];
    const float* Wo = (const float*)d_in[7];
    const float* bo = (const float*)d_in[8];
    float* out = (float*)d_out;

    half *xhi, *xlo, *wqh, *wql, *woh, *wol, *qkv, *ctx;
    cudaGetSymbolAddress((void**)&xhi, g_xhi);
    cudaGetSymbolAddress((void**)&xlo, g_xlo);
    cudaGetSymbolAddress((void**)&wqh, g_wqkv_hi);
    cudaGetSymbolAddress((void**)&wql, g_wqkv_lo);
    cudaGetSymbolAddress((void**)&woh, g_wo_hi);
    cudaGetSymbolAddress((void**)&wol, g_wo_lo);
    cudaGetSymbolAddress((void**)&qkv, g_qkv);
    cudaGetSymbolAddress((void**)&ctx, g_ctx);

    const int N4 = MTOT * D_ / 4;
    xsplit_kernel<<<(N4 + 255) / 256, 256>>>(x, xhi, xlo, N4);
    wsplit4_kernel<<<dim3(24, 24, 4), dim3(32, 8)>>>(Wq, Wk, Wv, Wo, wqh, wql, woh, wol);

    // QKV projection: xhi@Whi^T + xlo@Whi^T + xhi@Wlo^T  (3 segments)
    hgemm3<<<dim3(32, 18), 256>>>(xhi, xlo, xhi,
                                  wqh, wqh, wql,
                                  bq, bk, bv,
                                  qkv, 2304, 1, 3);

    attn_mma<<<dim3(S_ / 128, H_, 2), 256>>>(qkv, ctx);

    // output projection (fp32 out): ctx@Woh^T + ctx@Wol^T  (2 segments)
    hgemm3<<<dim3(32, 6), 256>>>(ctx, ctx, ctx,
                                 woh, wol, wol,
                                 bo, bo, bo,
                                 out, 768, 0, 2);
}